// round 6
// baseline (speedup 1.0000x reference)
#include <cuda_runtime.h>
#include <cuda_fp16.h>
#include <math.h>

#define NN 50000
#define FF 128
#define NE 800000
#define NT 5000
#define NCHUNK 49   // ceil(NN/1024)

// ---------------- static device scratch (no allocations allowed) ----------------
struct __align__(16) H2x4 { __half2 me01, me23, mx01, mx23; };
static __device__ H2x4 g_P[NN * 32];                 // packed (Me, Mx) fp16, 25.6 MB
static __device__ float g_Hn[NN * FF];               // normalized H (pre-GEMM)
static __device__ unsigned long long g_Wp[64 * FF];  // W pairs (even-f, odd-f), 64 KB
static __device__ int   g_cnt[NN];
static __device__ int   g_off[NN + 1];
static __device__ int   g_cur[NN];
static __device__ int2  g_cv[NE];                    // (col, val-bits)
static __device__ int   g_bsum[NCHUNK];
static __device__ int   g_mask[NN];

// ---------------- helpers ----------------
__device__ __forceinline__ float sigmoid_fast(float z) {
    return 1.0f / (1.0f + __expf(-z));
}
__device__ __forceinline__ float elu1(float v) {
    return v > 0.0f ? v : expm1f(v);
}
__device__ __forceinline__ unsigned long long pk2(float lo, float hi) {
    unsigned long long r;
    asm("mov.b64 %0, {%1, %2};" : "=l"(r) : "f"(lo), "f"(hi));
    return r;
}
__device__ __forceinline__ float2 unpk2(unsigned long long v) {
    float2 f;
    asm("mov.b64 {%0, %1}, %2;" : "=f"(f.x), "=f"(f.y) : "l"(v));
    return f;
}
__device__ __forceinline__ void fma2(unsigned long long& d, unsigned long long a, unsigned long long b) {
    asm("fma.rn.f32x2 %0, %1, %2, %0;" : "+l"(d) : "l"(a), "l"(b));
}

// ---------------- kernels ----------------
__global__ void k_zero() {
    int i = blockIdx.x * blockDim.x + threadIdx.x;
    if (i < NN) { g_cnt[i] = 0; g_mask[i] = 0; }
}

__global__ void k_mask(const int* __restrict__ tid) {
    int i = blockIdx.x * blockDim.x + threadIdx.x;
    if (i < NT) g_mask[tid[i]] = 1;
}

// pack W into even/odd-f pairs: g_Wp[f2*128+c] = (W[2f2][c], W[2f2+1][c])
__global__ void k_wpack(const float* __restrict__ W) {
    int i = blockIdx.x * blockDim.x + threadIdx.x;   // 0..8191
    if (i >= 64 * FF) return;
    int f2 = i >> 7, c = i & 127;
    g_Wp[i] = pk2(W[(2 * f2) * FF + c], W[(2 * f2 + 1) * FF + c]);
}

// M_eff = train ? 1 : sigmoid(M);  pack (Me, Me*x) quads to fp16
__global__ void k_meff(const float* __restrict__ x, const float* __restrict__ M) {
    int i = blockIdx.x * blockDim.x + threadIdx.x;   // quad index
    if (i >= NN * 32) return;
    int node = i >> 5;
    float4 m  = ((const float4*)M)[i];
    float4 xv = ((const float4*)x)[i];
    float4 me, mx;
    if (g_mask[node]) {
        me = make_float4(1.f, 1.f, 1.f, 1.f);
        mx = xv;
    } else {
        me.x = sigmoid_fast(m.x); me.y = sigmoid_fast(m.y);
        me.z = sigmoid_fast(m.z); me.w = sigmoid_fast(m.w);
        mx.x = me.x * xv.x; mx.y = me.y * xv.y;
        mx.z = me.z * xv.z; mx.w = me.w * xv.w;
    }
    H2x4 p;
    p.me01 = __floats2half2_rn(me.x, me.y);
    p.me23 = __floats2half2_rn(me.z, me.w);
    p.mx01 = __floats2half2_rn(mx.x, mx.y);
    p.mx23 = __floats2half2_rn(mx.z, mx.w);
    g_P[i] = p;
}

__global__ void k_hist(const int* __restrict__ erow) {
    int i = blockIdx.x * blockDim.x + threadIdx.x;
    if (i < NE / 2) {
        int2 r = ((const int2*)erow)[i];
        atomicAdd(&g_cnt[r.x], 1);
        atomicAdd(&g_cnt[r.y], 1);
    }
}

// per-chunk exclusive scan (1024-wide Hillis-Steele)
__global__ void k_scan1() {
    __shared__ int sh[1024];
    int t = threadIdx.x, b = blockIdx.x;
    int i = b * 1024 + t;
    int v = (i < NN) ? g_cnt[i] : 0;
    sh[t] = v;
    __syncthreads();
    for (int ofs = 1; ofs < 1024; ofs <<= 1) {
        int add = (t >= ofs) ? sh[t - ofs] : 0;
        __syncthreads();
        sh[t] += add;
        __syncthreads();
    }
    if (i < NN) g_off[i] = sh[t] - v;
    if (t == 1023) g_bsum[b] = sh[1023];
}

__global__ void k_scan2() {
    if (threadIdx.x == 0 && blockIdx.x == 0) {
        int acc = 0;
        for (int b = 0; b < NCHUNK; b++) {
            int v = g_bsum[b];
            g_bsum[b] = acc;
            acc += v;
        }
    }
}

__global__ void k_scan3() {
    int i = blockIdx.x * blockDim.x + threadIdx.x;
    if (i < NN) {
        int v = g_off[i] + g_bsum[i >> 10];
        g_off[i] = v;
        g_cur[i] = v;
    }
    if (i == 0) g_off[NN] = NE;
}

__global__ void k_scatter(const int* __restrict__ erow, const int* __restrict__ ecol,
                          const float* __restrict__ aval) {
    int i = blockIdx.x * blockDim.x + threadIdx.x;
    if (i >= NE / 2) return;
    int2   r = ((const int2*)erow)[i];
    int2   c = ((const int2*)ecol)[i];
    float2 w = ((const float2*)aval)[i];
    int p0 = atomicAdd(&g_cur[r.x], 1);
    g_cv[p0] = make_int2(c.x, __float_as_int(w.x));
    int p1 = atomicAdd(&g_cur[r.y], 1);
    g_cv[p1] = make_int2(c.y, __float_as_int(w.y));
}

// warp-per-row gather-reduce on packed fp16 (one LDG.128 per edge per lane)
__global__ void k_gather() {
    int gt   = blockIdx.x * blockDim.x + threadIdx.x;
    int row  = gt >> 5;
    int lane = gt & 31;
    if (row >= NN) return;
    int s = g_off[row], e = g_off[row + 1];
    float4 d = make_float4(0.f, 0.f, 0.f, 0.f);
    float4 h = make_float4(0.f, 0.f, 0.f, 0.f);
    int j = s;
    for (; j + 3 < e; j += 4) {
        int2 cv0 = __ldg(&g_cv[j]);
        int2 cv1 = __ldg(&g_cv[j + 1]);
        int2 cv2 = __ldg(&g_cv[j + 2]);
        int2 cv3 = __ldg(&g_cv[j + 3]);
        H2x4 p0 = g_P[cv0.x * 32 + lane];
        H2x4 p1 = g_P[cv1.x * 32 + lane];
        H2x4 p2 = g_P[cv2.x * 32 + lane];
        H2x4 p3 = g_P[cv3.x * 32 + lane];
        float w0 = __int_as_float(cv0.y), w1 = __int_as_float(cv1.y);
        float w2 = __int_as_float(cv2.y), w3 = __int_as_float(cv3.y);
        float2 a, b;
        a = __half22float2(p0.me01); b = __half22float2(p0.me23);
        d.x += a.x; d.y += a.y; d.z += b.x; d.w += b.y;
        a = __half22float2(p0.mx01); b = __half22float2(p0.mx23);
        h.x += w0 * a.x; h.y += w0 * a.y; h.z += w0 * b.x; h.w += w0 * b.y;
        a = __half22float2(p1.me01); b = __half22float2(p1.me23);
        d.x += a.x; d.y += a.y; d.z += b.x; d.w += b.y;
        a = __half22float2(p1.mx01); b = __half22float2(p1.mx23);
        h.x += w1 * a.x; h.y += w1 * a.y; h.z += w1 * b.x; h.w += w1 * b.y;
        a = __half22float2(p2.me01); b = __half22float2(p2.me23);
        d.x += a.x; d.y += a.y; d.z += b.x; d.w += b.y;
        a = __half22float2(p2.mx01); b = __half22float2(p2.mx23);
        h.x += w2 * a.x; h.y += w2 * a.y; h.z += w2 * b.x; h.w += w2 * b.y;
        a = __half22float2(p3.me01); b = __half22float2(p3.me23);
        d.x += a.x; d.y += a.y; d.z += b.x; d.w += b.y;
        a = __half22float2(p3.mx01); b = __half22float2(p3.mx23);
        h.x += w3 * a.x; h.y += w3 * a.y; h.z += w3 * b.x; h.w += w3 * b.y;
    }
    for (; j < e; ++j) {
        int2 cv = __ldg(&g_cv[j]);
        H2x4 p = g_P[cv.x * 32 + lane];
        float w = __int_as_float(cv.y);
        float2 a, b;
        a = __half22float2(p.me01); b = __half22float2(p.me23);
        d.x += a.x; d.y += a.y; d.z += b.x; d.w += b.y;
        a = __half22float2(p.mx01); b = __half22float2(p.mx23);
        h.x += w * a.x; h.y += w * a.y; h.z += w * b.x; h.w += w * b.y;
    }
    float4 o;
    o.x = (d.x != 0.f) ? h.x * __fdividef(1.f, d.x) : 0.f;
    o.y = (d.y != 0.f) ? h.y * __fdividef(1.f, d.y) : 0.f;
    o.z = (d.z != 0.f) ? h.z * __fdividef(1.f, d.z) : 0.f;
    o.w = (d.w != 0.f) ? h.w * __fdividef(1.f, d.w) : 0.f;
    *(float4*)&g_Hn[row * FF + lane * 4] = o;
}

// out = elu(Hn @ W) using fma.rn.f32x2 paired over K (even/odd-f partial sums).
// 256 threads, 32 rows x 128 cols tile; thread: rows {ty,ty+8,ty+16,ty+24}, cols 4tx..4tx+3
__global__ void k_gemm(float* __restrict__ out) {
    __shared__ float Hs[32][FF];
    int r0 = blockIdx.x * 32;
    int t  = threadIdx.x;

    for (int i = t; i < 32 * FF / 4; i += 256) {
        int row  = (i * 4) / FF;
        int colf = (i * 4) % FF;
        float4 v = (r0 + row < NN) ? *(const float4*)&g_Hn[(r0 + row) * FF + colf]
                                   : make_float4(0.f, 0.f, 0.f, 0.f);
        *(float4*)&Hs[row][colf] = v;
    }
    __syncthreads();

    int tx = t & 31;
    int ty = t >> 5;
    unsigned long long acc[4][4];
    #pragma unroll
    for (int a = 0; a < 4; a++)
        #pragma unroll
        for (int b = 0; b < 4; b++) acc[a][b] = 0ULL;

    #pragma unroll 4
    for (int f2 = 0; f2 < 64; ++f2) {
        ulonglong2 wa = *(const ulonglong2*)&g_Wp[f2 * FF + tx * 4];
        ulonglong2 wb = *(const ulonglong2*)&g_Wp[f2 * FF + tx * 4 + 2];
        #pragma unroll
        for (int rr = 0; rr < 4; ++rr) {
            unsigned long long hp = *(const unsigned long long*)&Hs[ty + rr * 8][2 * f2];
            fma2(acc[rr][0], hp, wa.x);
            fma2(acc[rr][1], hp, wa.y);
            fma2(acc[rr][2], hp, wb.x);
            fma2(acc[rr][3], hp, wb.y);
        }
    }

    #pragma unroll
    for (int rr = 0; rr < 4; ++rr) {
        int row = r0 + ty + rr * 8;
        if (row < NN) {
            float4 v;
            float2 p;
            p = unpk2(acc[rr][0]); v.x = elu1(p.x + p.y);
            p = unpk2(acc[rr][1]); v.y = elu1(p.x + p.y);
            p = unpk2(acc[rr][2]); v.z = elu1(p.x + p.y);
            p = unpk2(acc[rr][3]); v.w = elu1(p.x + p.y);
            *(float4*)&out[row * FF + tx * 4] = v;
        }
    }
}

// ---------------- launch ----------------
extern "C" void kernel_launch(void* const* d_in, const int* in_sizes, int n_in,
                              void* d_out, int out_size) {
    const float* x    = (const float*)d_in[0];
    const int*   erow = (const int*)  d_in[1];
    const int*   ecol = (const int*)  d_in[2];
    const float* aval = (const float*)d_in[3];
    const int*   tid  = (const int*)  d_in[4];
    const float* M    = (const float*)d_in[5];
    const float* W    = (const float*)d_in[6];
    float*       out  = (float*)d_out;

    k_zero   <<<(NN + 255) / 256, 256>>>();
    k_mask   <<<(NT + 255) / 256, 256>>>(tid);
    k_wpack  <<<(64 * FF + 255) / 256, 256>>>(W);
    k_meff   <<<(NN * 32 + 255) / 256, 256>>>(x, M);
    k_hist   <<<(NE / 2 + 255) / 256, 256>>>(erow);
    k_scan1  <<<NCHUNK, 1024>>>();
    k_scan2  <<<1, 32>>>();
    k_scan3  <<<(NN + 255) / 256, 256>>>();
    k_scatter<<<(NE / 2 + 255) / 256, 256>>>(erow, ecol, aval);
    k_gather <<<(NN * 32 + 255) / 256, 256>>>();
    k_gemm   <<<(NN + 31) / 32, 256>>>(out);
}

// round 7
// speedup vs baseline: 1.0621x; 1.0621x over previous
#include <cuda_runtime.h>
#include <cuda_fp16.h>
#include <math.h>

#define NN 50000
#define FF 128
#define NE 800000
#define NT 5000
#define NCHUNK 49   // ceil(NN/1024)
#define NWP (64 * FF)          // 8192 W-pairs
#define SCAT_T (NE / 2)        // 400000 scatter threads
#define MEFF_T (NN * 32)       // 1600000 meff quad threads

// ---------------- static device scratch (no allocations allowed) ----------------
struct __align__(16) H2x4 { __half2 me01, me23, mx01, mx23; };
static __device__ H2x4 g_P[NN * 32];                 // packed (Me, Mx) fp16, 25.6 MB
static __device__ float g_Hn[NN * FF];               // normalized H (pre-GEMM)
static __device__ unsigned long long g_Wp[NWP];      // W pairs (even-f, odd-f), 64 KB
static __device__ int   g_cnt[NN];
static __device__ int   g_off[NN + 1];
static __device__ int   g_cur[NN];
static __device__ int2  g_cv[NE];                    // (col, val-bits)
static __device__ int   g_bsum[NCHUNK];
static __device__ int   g_mask[NN];

// ---------------- helpers ----------------
__device__ __forceinline__ float sigmoid_fast(float z) {
    return 1.0f / (1.0f + __expf(-z));
}
__device__ __forceinline__ float elu1(float v) {
    return v > 0.0f ? v : expm1f(v);
}
__device__ __forceinline__ unsigned long long pk2(float lo, float hi) {
    unsigned long long r;
    asm("mov.b64 %0, {%1, %2};" : "=l"(r) : "f"(lo), "f"(hi));
    return r;
}
__device__ __forceinline__ float2 unpk2(unsigned long long v) {
    float2 f;
    asm("mov.b64 {%0, %1}, %2;" : "=f"(f.x), "=f"(f.y) : "l"(v));
    return f;
}
__device__ __forceinline__ void fma2(unsigned long long& d, unsigned long long a, unsigned long long b) {
    asm("fma.rn.f32x2 %0, %1, %2, %0;" : "+l"(d) : "l"(a), "l"(b));
}

// ---------------- fused kernels ----------------
// L1: zero counters/mask + pack W
__global__ void k_init(const float* __restrict__ W) {
    int i = blockIdx.x * blockDim.x + threadIdx.x;
    if (i < NN) { g_cnt[i] = 0; g_mask[i] = 0; }
    int j = i - NN;
    if (j >= 0 && j < NWP) {
        int f2 = j >> 7, c = j & 127;
        g_Wp[j] = pk2(W[(2 * f2) * FF + c], W[(2 * f2 + 1) * FF + c]);
    }
}

// L2: train-mask scatter + degree histogram (independent; one launch)
__global__ void k_mask_hist(const int* __restrict__ tid, const int* __restrict__ erow) {
    int i = blockIdx.x * blockDim.x + threadIdx.x;
    if (i < NT) {
        g_mask[tid[i]] = 1;
    } else {
        int j = i - NT;
        if (j < NE / 2) {
            int2 r = ((const int2*)erow)[j];
            atomicAdd(&g_cnt[r.x], 1);
            atomicAdd(&g_cnt[r.y], 1);
        }
    }
}

// L3: per-chunk exclusive scan (1024-wide Hillis-Steele)
__global__ void k_scan1() {
    __shared__ int sh[1024];
    int t = threadIdx.x, b = blockIdx.x;
    int i = b * 1024 + t;
    int v = (i < NN) ? g_cnt[i] : 0;
    sh[t] = v;
    __syncthreads();
    for (int ofs = 1; ofs < 1024; ofs <<= 1) {
        int add = (t >= ofs) ? sh[t - ofs] : 0;
        __syncthreads();
        sh[t] += add;
        __syncthreads();
    }
    if (i < NN) g_off[i] = sh[t] - v;
    if (t == 1023) g_bsum[b] = sh[1023];
}

// L4: chunk-prefix (fused old scan2) + final offsets. 256-thread blocks never
// straddle a 1024-chunk boundary, so one prefix per block suffices.
__global__ void k_scan23() {
    __shared__ int pre;
    int i = blockIdx.x * blockDim.x + threadIdx.x;
    if (threadIdx.x == 0) {
        int chunk = i >> 10, acc = 0;
        for (int b = 0; b < chunk; b++) acc += g_bsum[b];
        pre = acc;
    }
    __syncthreads();
    if (i < NN) {
        int v = g_off[i] + pre;
        g_off[i] = v;
        g_cur[i] = v;
    }
    if (i == 0) g_off[NN] = NE;
}

// L5: CSR scatter (atomics, latency-bound) overlapped with meff (DRAM-bound)
__global__ void k_scatter_meff(const int* __restrict__ erow, const int* __restrict__ ecol,
                               const float* __restrict__ aval,
                               const float* __restrict__ x, const float* __restrict__ M) {
    int gi = blockIdx.x * blockDim.x + threadIdx.x;
    if (gi < SCAT_T) {
        int2   r = ((const int2*)erow)[gi];
        int2   c = ((const int2*)ecol)[gi];
        float2 w = ((const float2*)aval)[gi];
        int p0 = atomicAdd(&g_cur[r.x], 1);
        g_cv[p0] = make_int2(c.x, __float_as_int(w.x));
        int p1 = atomicAdd(&g_cur[r.y], 1);
        g_cv[p1] = make_int2(c.y, __float_as_int(w.y));
        return;
    }
    int i = gi - SCAT_T;
    if (i >= MEFF_T) return;
    int node = i >> 5;
    float4 m  = ((const float4*)M)[i];
    float4 xv = ((const float4*)x)[i];
    float4 me, mx;
    if (g_mask[node]) {
        me = make_float4(1.f, 1.f, 1.f, 1.f);
        mx = xv;
    } else {
        me.x = sigmoid_fast(m.x); me.y = sigmoid_fast(m.y);
        me.z = sigmoid_fast(m.z); me.w = sigmoid_fast(m.w);
        mx.x = me.x * xv.x; mx.y = me.y * xv.y;
        mx.z = me.z * xv.z; mx.w = me.w * xv.w;
    }
    H2x4 p;
    p.me01 = __floats2half2_rn(me.x, me.y);
    p.me23 = __floats2half2_rn(me.z, me.w);
    p.mx01 = __floats2half2_rn(mx.x, mx.y);
    p.mx23 = __floats2half2_rn(mx.z, mx.w);
    g_P[i] = p;
}

// L6: warp-per-row gather-reduce on packed fp16 (one LDG.128 per edge per lane)
__global__ void k_gather() {
    int gt   = blockIdx.x * blockDim.x + threadIdx.x;
    int row  = gt >> 5;
    int lane = gt & 31;
    if (row >= NN) return;
    int s = g_off[row], e = g_off[row + 1];
    float4 d = make_float4(0.f, 0.f, 0.f, 0.f);
    float4 h = make_float4(0.f, 0.f, 0.f, 0.f);
    int j = s;
    for (; j + 3 < e; j += 4) {
        int2 cv0 = __ldg(&g_cv[j]);
        int2 cv1 = __ldg(&g_cv[j + 1]);
        int2 cv2 = __ldg(&g_cv[j + 2]);
        int2 cv3 = __ldg(&g_cv[j + 3]);
        H2x4 p0 = g_P[cv0.x * 32 + lane];
        H2x4 p1 = g_P[cv1.x * 32 + lane];
        H2x4 p2 = g_P[cv2.x * 32 + lane];
        H2x4 p3 = g_P[cv3.x * 32 + lane];
        float w0 = __int_as_float(cv0.y), w1 = __int_as_float(cv1.y);
        float w2 = __int_as_float(cv2.y), w3 = __int_as_float(cv3.y);
        float2 a, b;
        a = __half22float2(p0.me01); b = __half22float2(p0.me23);
        d.x += a.x; d.y += a.y; d.z += b.x; d.w += b.y;
        a = __half22float2(p0.mx01); b = __half22float2(p0.mx23);
        h.x += w0 * a.x; h.y += w0 * a.y; h.z += w0 * b.x; h.w += w0 * b.y;
        a = __half22float2(p1.me01); b = __half22float2(p1.me23);
        d.x += a.x; d.y += a.y; d.z += b.x; d.w += b.y;
        a = __half22float2(p1.mx01); b = __half22float2(p1.mx23);
        h.x += w1 * a.x; h.y += w1 * a.y; h.z += w1 * b.x; h.w += w1 * b.y;
        a = __half22float2(p2.me01); b = __half22float2(p2.me23);
        d.x += a.x; d.y += a.y; d.z += b.x; d.w += b.y;
        a = __half22float2(p2.mx01); b = __half22float2(p2.mx23);
        h.x += w2 * a.x; h.y += w2 * a.y; h.z += w2 * b.x; h.w += w2 * b.y;
        a = __half22float2(p3.me01); b = __half22float2(p3.me23);
        d.x += a.x; d.y += a.y; d.z += b.x; d.w += b.y;
        a = __half22float2(p3.mx01); b = __half22float2(p3.mx23);
        h.x += w3 * a.x; h.y += w3 * a.y; h.z += w3 * b.x; h.w += w3 * b.y;
    }
    for (; j < e; ++j) {
        int2 cv = __ldg(&g_cv[j]);
        H2x4 p = g_P[cv.x * 32 + lane];
        float w = __int_as_float(cv.y);
        float2 a, b;
        a = __half22float2(p.me01); b = __half22float2(p.me23);
        d.x += a.x; d.y += a.y; d.z += b.x; d.w += b.y;
        a = __half22float2(p.mx01); b = __half22float2(p.mx23);
        h.x += w * a.x; h.y += w * a.y; h.z += w * b.x; h.w += w * b.y;
    }
    float4 o;
    o.x = (d.x != 0.f) ? h.x * __fdividef(1.f, d.x) : 0.f;
    o.y = (d.y != 0.f) ? h.y * __fdividef(1.f, d.y) : 0.f;
    o.z = (d.z != 0.f) ? h.z * __fdividef(1.f, d.z) : 0.f;
    o.w = (d.w != 0.f) ? h.w * __fdividef(1.f, d.w) : 0.f;
    *(float4*)&g_Hn[row * FF + lane * 4] = o;
}

// L7: out = elu(Hn @ W) with fma.rn.f32x2 paired over K.
__global__ void k_gemm(float* __restrict__ out) {
    __shared__ float Hs[32][FF];
    int r0 = blockIdx.x * 32;
    int t  = threadIdx.x;

    for (int i = t; i < 32 * FF / 4; i += 256) {
        int row  = (i * 4) / FF;
        int colf = (i * 4) % FF;
        float4 v = (r0 + row < NN) ? *(const float4*)&g_Hn[(r0 + row) * FF + colf]
                                   : make_float4(0.f, 0.f, 0.f, 0.f);
        *(float4*)&Hs[row][colf] = v;
    }
    __syncthreads();

    int tx = t & 31;
    int ty = t >> 5;
    unsigned long long acc[4][4];
    #pragma unroll
    for (int a = 0; a < 4; a++)
        #pragma unroll
        for (int b = 0; b < 4; b++) acc[a][b] = 0ULL;

    #pragma unroll 4
    for (int f2 = 0; f2 < 64; ++f2) {
        ulonglong2 wa = __ldg((const ulonglong2*)&g_Wp[f2 * FF + tx * 4]);
        ulonglong2 wb = __ldg((const ulonglong2*)&g_Wp[f2 * FF + tx * 4 + 2]);
        #pragma unroll
        for (int rr = 0; rr < 4; ++rr) {
            unsigned long long hp = *(const unsigned long long*)&Hs[ty + rr * 8][2 * f2];
            fma2(acc[rr][0], hp, wa.x);
            fma2(acc[rr][1], hp, wa.y);
            fma2(acc[rr][2], hp, wb.x);
            fma2(acc[rr][3], hp, wb.y);
        }
    }

    #pragma unroll
    for (int rr = 0; rr < 4; ++rr) {
        int row = r0 + ty + rr * 8;
        if (row < NN) {
            float4 v;
            float2 p;
            p = unpk2(acc[rr][0]); v.x = elu1(p.x + p.y);
            p = unpk2(acc[rr][1]); v.y = elu1(p.x + p.y);
            p = unpk2(acc[rr][2]); v.z = elu1(p.x + p.y);
            p = unpk2(acc[rr][3]); v.w = elu1(p.x + p.y);
            *(float4*)&out[row * FF + tx * 4] = v;
        }
    }
}

// ---------------- launch ----------------
extern "C" void kernel_launch(void* const* d_in, const int* in_sizes, int n_in,
                              void* d_out, int out_size) {
    const float* x    = (const float*)d_in[0];
    const int*   erow = (const int*)  d_in[1];
    const int*   ecol = (const int*)  d_in[2];
    const float* aval = (const float*)d_in[3];
    const int*   tid  = (const int*)  d_in[4];
    const float* M    = (const float*)d_in[5];
    const float* W    = (const float*)d_in[6];
    float*       out  = (float*)d_out;

    k_init        <<<(NN + NWP + 255) / 256, 256>>>(W);
    k_mask_hist   <<<(NT + NE / 2 + 255) / 256, 256>>>(tid, erow);
    k_scan1       <<<NCHUNK, 1024>>>();
    k_scan23      <<<(NN + 255) / 256, 256>>>();
    k_scatter_meff<<<(SCAT_T + MEFF_T + 255) / 256, 256>>>(erow, ecol, aval, x, M);
    k_gather      <<<(NN * 32 + 255) / 256, 256>>>();
    k_gemm        <<<(NN + 31) / 32, 256>>>(out);
}

// round 8
// speedup vs baseline: 1.6760x; 1.5780x over previous
#include <cuda_runtime.h>
#include <cuda_fp16.h>
#include <math.h>

#define NN 50000
#define FF 128
#define NE 800000
#define NT 5000
#define NCHUNK 49              // ceil(NN/1024)
#define NWF 4096               // 8 ksteps * 16 ntiles * 32 lanes
#define SCAT_T (NE / 2)        // 400000 scatter threads
#define MEFF_T (NN * 32)       // 1600000 meff quad threads
#define GROWS 64               // gemm rows per block
#define HS_STRIDE 136          // padded fp16 row stride in smem

// ---------------- static device scratch (no allocations allowed) ----------------
struct __align__(16) H2x4 { __half2 me01, me23, mx01, mx23; };
static __device__ H2x4  g_P[NN * 32];    // packed (Me, Mx) fp16, 25.6 MB
static __device__ __half g_Hh[NN * FF];  // normalized H, fp16, 12.8 MB
static __device__ uint2 g_Wf[NWF];       // W fp16 in mma B-fragment layout, 32 KB
static __device__ int   g_cnt[NN];
static __device__ int   g_off[NN + 1];
static __device__ int   g_cur[NN];
static __device__ int2  g_cv[NE];        // (col, val-bits)
static __device__ int   g_bsum[NCHUNK];
static __device__ int   g_mask[NN];

// ---------------- helpers ----------------
__device__ __forceinline__ float sigmoid_fast(float z) {
    return 1.0f / (1.0f + __expf(-z));
}
__device__ __forceinline__ float elu1(float v) {
    return v > 0.0f ? v : expm1f(v);
}
__device__ __forceinline__ void ldm_x4(unsigned& r0, unsigned& r1, unsigned& r2, unsigned& r3,
                                       unsigned addr) {
    asm volatile("ldmatrix.sync.aligned.m8n8.x4.shared.b16 {%0,%1,%2,%3}, [%4];"
                 : "=r"(r0), "=r"(r1), "=r"(r2), "=r"(r3) : "r"(addr));
}
__device__ __forceinline__ void mma16816(float* c, const unsigned* a, unsigned b0, unsigned b1) {
    asm volatile(
        "mma.sync.aligned.m16n8k16.row.col.f32.f16.f16.f32 "
        "{%0,%1,%2,%3}, {%4,%5,%6,%7}, {%8,%9}, {%0,%1,%2,%3};"
        : "+f"(c[0]), "+f"(c[1]), "+f"(c[2]), "+f"(c[3])
        : "r"(a[0]), "r"(a[1]), "r"(a[2]), "r"(a[3]), "r"(b0), "r"(b1));
}

// ---------------- kernels ----------------
// L1: zero counters/mask + build W mma-fragment table
__global__ void k_init(const float* __restrict__ W) {
    int i = blockIdx.x * blockDim.x + threadIdx.x;
    if (i < NN) { g_cnt[i] = 0; g_mask[i] = 0; }
    int j = i - NN;
    if (j >= 0 && j < NWF) {
        int lane = j & 31, ntg = (j >> 5) & 15, ks = j >> 9;
        int n  = ntg * 8 + (lane >> 2);
        int tq = lane & 3;
        int k0 = ks * 16 + tq * 2;
        __half2 b0 = __floats2half2_rn(W[k0 * FF + n],       W[(k0 + 1) * FF + n]);
        __half2 b1 = __floats2half2_rn(W[(k0 + 8) * FF + n], W[(k0 + 9) * FF + n]);
        uint2 o;
        o.x = *(const unsigned*)&b0;
        o.y = *(const unsigned*)&b1;
        g_Wf[j] = o;
    }
}

// L2: train-mask scatter + degree histogram (independent; one launch)
__global__ void k_mask_hist(const int* __restrict__ tid, const int* __restrict__ erow) {
    int i = blockIdx.x * blockDim.x + threadIdx.x;
    if (i < NT) {
        g_mask[tid[i]] = 1;
    } else {
        int j = i - NT;
        if (j < NE / 2) {
            int2 r = ((const int2*)erow)[j];
            atomicAdd(&g_cnt[r.x], 1);
            atomicAdd(&g_cnt[r.y], 1);
        }
    }
}

// L3: per-chunk exclusive scan (1024-wide Hillis-Steele)
__global__ void k_scan1() {
    __shared__ int sh[1024];
    int t = threadIdx.x, b = blockIdx.x;
    int i = b * 1024 + t;
    int v = (i < NN) ? g_cnt[i] : 0;
    sh[t] = v;
    __syncthreads();
    for (int ofs = 1; ofs < 1024; ofs <<= 1) {
        int add = (t >= ofs) ? sh[t - ofs] : 0;
        __syncthreads();
        sh[t] += add;
        __syncthreads();
    }
    if (i < NN) g_off[i] = sh[t] - v;
    if (t == 1023) g_bsum[b] = sh[1023];
}

// L4: chunk-prefix (parallel 64-thread reduce) + final offsets
__global__ void k_scan23() {
    __shared__ int spre[2];
    int t = threadIdx.x;
    int i = blockIdx.x * 256 + t;
    if (t < 64) {
        int chunk = (blockIdx.x << 8) >> 10;
        int v = (t < chunk) ? g_bsum[t] : 0;
        #pragma unroll
        for (int o = 16; o; o >>= 1) v += __shfl_down_sync(0xffffffffu, v, o);
        if ((t & 31) == 0) spre[t >> 5] = v;
    }
    __syncthreads();
    int pre = spre[0] + spre[1];
    if (i < NN) {
        int v = g_off[i] + pre;
        g_off[i] = v;
        g_cur[i] = v;
    }
    if (i == 0) g_off[NN] = NE;
}

// L5: CSR scatter (atomics, latency-bound) overlapped with meff (DRAM-bound)
__global__ void k_scatter_meff(const int* __restrict__ erow, const int* __restrict__ ecol,
                               const float* __restrict__ aval,
                               const float* __restrict__ x, const float* __restrict__ M) {
    int gi = blockIdx.x * blockDim.x + threadIdx.x;
    if (gi < SCAT_T) {
        int2   r = ((const int2*)erow)[gi];
        int2   c = ((const int2*)ecol)[gi];
        float2 w = ((const float2*)aval)[gi];
        int p0 = atomicAdd(&g_cur[r.x], 1);
        g_cv[p0] = make_int2(c.x, __float_as_int(w.x));
        int p1 = atomicAdd(&g_cur[r.y], 1);
        g_cv[p1] = make_int2(c.y, __float_as_int(w.y));
        return;
    }
    int i = gi - SCAT_T;
    if (i >= MEFF_T) return;
    int node = i >> 5;
    float4 m  = ((const float4*)M)[i];
    float4 xv = ((const float4*)x)[i];
    float4 me, mx;
    if (g_mask[node]) {
        me = make_float4(1.f, 1.f, 1.f, 1.f);
        mx = xv;
    } else {
        me.x = sigmoid_fast(m.x); me.y = sigmoid_fast(m.y);
        me.z = sigmoid_fast(m.z); me.w = sigmoid_fast(m.w);
        mx.x = me.x * xv.x; mx.y = me.y * xv.y;
        mx.z = me.z * xv.z; mx.w = me.w * xv.w;
    }
    H2x4 p;
    p.me01 = __floats2half2_rn(me.x, me.y);
    p.me23 = __floats2half2_rn(me.z, me.w);
    p.mx01 = __floats2half2_rn(mx.x, mx.y);
    p.mx23 = __floats2half2_rn(mx.z, mx.w);
    g_P[i] = p;
}

// L6: warp-per-row gather-reduce on packed fp16; writes Hn as fp16
__global__ void k_gather() {
    int gt   = blockIdx.x * blockDim.x + threadIdx.x;
    int row  = gt >> 5;
    int lane = gt & 31;
    if (row >= NN) return;
    int s = g_off[row], e = g_off[row + 1];
    float4 d = make_float4(0.f, 0.f, 0.f, 0.f);
    float4 h = make_float4(0.f, 0.f, 0.f, 0.f);
    int j = s;
    for (; j + 3 < e; j += 4) {
        int2 cv0 = __ldg(&g_cv[j]);
        int2 cv1 = __ldg(&g_cv[j + 1]);
        int2 cv2 = __ldg(&g_cv[j + 2]);
        int2 cv3 = __ldg(&g_cv[j + 3]);
        H2x4 p0 = g_P[cv0.x * 32 + lane];
        H2x4 p1 = g_P[cv1.x * 32 + lane];
        H2x4 p2 = g_P[cv2.x * 32 + lane];
        H2x4 p3 = g_P[cv3.x * 32 + lane];
        float w0 = __int_as_float(cv0.y), w1 = __int_as_float(cv1.y);
        float w2 = __int_as_float(cv2.y), w3 = __int_as_float(cv3.y);
        float2 a, b;
        a = __half22float2(p0.me01); b = __half22float2(p0.me23);
        d.x += a.x; d.y += a.y; d.z += b.x; d.w += b.y;
        a = __half22float2(p0.mx01); b = __half22float2(p0.mx23);
        h.x += w0 * a.x; h.y += w0 * a.y; h.z += w0 * b.x; h.w += w0 * b.y;
        a = __half22float2(p1.me01); b = __half22float2(p1.me23);
        d.x += a.x; d.y += a.y; d.z += b.x; d.w += b.y;
        a = __half22float2(p1.mx01); b = __half22float2(p1.mx23);
        h.x += w1 * a.x; h.y += w1 * a.y; h.z += w1 * b.x; h.w += w1 * b.y;
        a = __half22float2(p2.me01); b = __half22float2(p2.me23);
        d.x += a.x; d.y += a.y; d.z += b.x; d.w += b.y;
        a = __half22float2(p2.mx01); b = __half22float2(p2.mx23);
        h.x += w2 * a.x; h.y += w2 * a.y; h.z += w2 * b.x; h.w += w2 * b.y;
        a = __half22float2(p3.me01); b = __half22float2(p3.me23);
        d.x += a.x; d.y += a.y; d.z += b.x; d.w += b.y;
        a = __half22float2(p3.mx01); b = __half22float2(p3.mx23);
        h.x += w3 * a.x; h.y += w3 * a.y; h.z += w3 * b.x; h.w += w3 * b.y;
    }
    for (; j < e; ++j) {
        int2 cv = __ldg(&g_cv[j]);
        H2x4 p = g_P[cv.x * 32 + lane];
        float w = __int_as_float(cv.y);
        float2 a, b;
        a = __half22float2(p.me01); b = __half22float2(p.me23);
        d.x += a.x; d.y += a.y; d.z += b.x; d.w += b.y;
        a = __half22float2(p.mx01); b = __half22float2(p.mx23);
        h.x += w * a.x; h.y += w * a.y; h.z += w * b.x; h.w += w * b.y;
    }
    float4 o;
    o.x = (d.x != 0.f) ? h.x * __fdividef(1.f, d.x) : 0.f;
    o.y = (d.y != 0.f) ? h.y * __fdividef(1.f, d.y) : 0.f;
    o.z = (d.z != 0.f) ? h.z * __fdividef(1.f, d.z) : 0.f;
    o.w = (d.w != 0.f) ? h.w * __fdividef(1.f, d.w) : 0.f;
    __half2 h01 = __floats2half2_rn(o.x, o.y);
    __half2 h23 = __floats2half2_rn(o.z, o.w);
    uint2 ph;
    ph.x = *(const unsigned*)&h01;
    ph.y = *(const unsigned*)&h23;
    *(uint2*)&g_Hh[row * FF + lane * 4] = ph;
}

// L7: out = elu(Hh @ W) via mma.sync m16n8k16 fp16->fp32.
// 256 thr / 8 warps; tile 64 rows x 128 cols; warp = 16 rows x 64 cols.
__global__ void k_gemm(float* __restrict__ out) {
    __shared__ __half Hs[GROWS * HS_STRIDE];
    int r0 = blockIdx.x * GROWS;
    int t  = threadIdx.x;

    // cooperative load: 64 rows x 16 uint4 (8 fp16 each)
    for (int i = t; i < GROWS * 16; i += 256) {
        int row = i >> 4, c8 = (i & 15) * 8;
        uint4 v = (r0 + row < NN) ? *(const uint4*)&g_Hh[(r0 + row) * FF + c8]
                                  : make_uint4(0u, 0u, 0u, 0u);
        *(uint4*)&Hs[row * HS_STRIDE + c8] = v;
    }
    __syncthreads();

    int wid = t >> 5, lane = t & 31;
    int wm = wid >> 1, wn = wid & 1;

    // A fragments for all 8 k-steps via ldmatrix.x4
    unsigned a[8][4];
    int sub = lane >> 3, rr = lane & 7;
    int arow = wm * 16 + rr + (sub & 1) * 8;
    int acol = (sub >> 1) * 8;
    #pragma unroll
    for (int ks = 0; ks < 8; ks++) {
        unsigned addr = (unsigned)__cvta_generic_to_shared(&Hs[arow * HS_STRIDE + ks * 16 + acol]);
        ldm_x4(a[ks][0], a[ks][1], a[ks][2], a[ks][3], addr);
    }

    float acc[8][4] = {};
    #pragma unroll
    for (int ks = 0; ks < 8; ks++) {
        #pragma unroll
        for (int nt = 0; nt < 8; nt++) {
            uint2 b = __ldg(&g_Wf[(ks * 16 + wn * 8 + nt) * 32 + lane]);
            mma16816(acc[nt], a[ks], b.x, b.y);
        }
    }

    int g = lane >> 2, tq = lane & 3;
    int row0 = r0 + wm * 16 + g;
    int row1 = row0 + 8;
    #pragma unroll
    for (int nt = 0; nt < 8; nt++) {
        int col = wn * 64 + nt * 8 + 2 * tq;
        if (row0 < NN) {
            float2 v;
            v.x = elu1(acc[nt][0]);
            v.y = elu1(acc[nt][1]);
            *(float2*)&out[row0 * FF + col] = v;
        }
        if (row1 < NN) {
            float2 v;
            v.x = elu1(acc[nt][2]);
            v.y = elu1(acc[nt][3]);
            *(float2*)&out[row1 * FF + col] = v;
        }
    }
}

// ---------------- launch ----------------
extern "C" void kernel_launch(void* const* d_in, const int* in_sizes, int n_in,
                              void* d_out, int out_size) {
    const float* x    = (const float*)d_in[0];
    const int*   erow = (const int*)  d_in[1];
    const int*   ecol = (const int*)  d_in[2];
    const float* aval = (const float*)d_in[3];
    const int*   tid  = (const int*)  d_in[4];
    const float* M    = (const float*)d_in[5];
    const float* W    = (const float*)d_in[6];
    float*       out  = (float*)d_out;

    k_init        <<<(NN + NWF + 255) / 256, 256>>>(W);
    k_mask_hist   <<<(NT + NE / 2 + 255) / 256, 256>>>(tid, erow);
    k_scan1       <<<NCHUNK, 1024>>>();
    k_scan23      <<<(NN + 255) / 256, 256>>>();
    k_scatter_meff<<<(SCAT_T + MEFF_T + 255) / 256, 256>>>(erow, ecol, aval, x, M);
    k_gather      <<<(NN * 32 + 255) / 256, 256>>>();
    k_gemm        <<<(NN + GROWS - 1) / GROWS, 256>>>(out);
}

// round 9
// speedup vs baseline: 1.7870x; 1.0662x over previous
#include <cuda_runtime.h>
#include <cuda_fp16.h>
#include <math.h>

#define NN 50000
#define FF 128
#define NE 800000
#define NT 5000
#define NWF 4096               // 8 ksteps * 16 ntiles * 32 lanes
#define SCAT_T (NE / 2)        // 400000 scatter threads (2 edges each)
#define MEFF_T (NN * 32)       // 1600000 meff quad threads
#define MAXDEG 128             // padded CSR row capacity (P(overflow) ~ 1e-68)
#define GROWS 64               // gemm rows per block
#define HS_STRIDE 136          // padded fp16 row stride in smem

// ---------------- static device scratch (no allocations allowed) ----------------
struct __align__(16) H2x4 { __half2 me01, me23, mx01, mx23; };
static __device__ H2x4  g_P[NN * 32];          // packed (Me, Mx) fp16, 25.6 MB
static __device__ __half g_Hh[NN * FF];        // normalized H, fp16, 12.8 MB
static __device__ uint2 g_Wf[NWF];             // W fp16 in mma B-fragment layout, 32 KB
static __device__ int   g_cnt[NN];             // degree counter / CSR fill cursor
static __device__ int2  g_cv[NN * MAXDEG];     // padded CSR (col, val-bits), 51.2 MB

// ---------------- helpers ----------------
__device__ __forceinline__ float sigmoid_fast(float z) {
    return 1.0f / (1.0f + __expf(-z));
}
__device__ __forceinline__ float elu1(float v) {
    return v > 0.0f ? v : expm1f(v);
}
__device__ __forceinline__ void ldm_x4(unsigned& r0, unsigned& r1, unsigned& r2, unsigned& r3,
                                       unsigned addr) {
    asm volatile("ldmatrix.sync.aligned.m8n8.x4.shared.b16 {%0,%1,%2,%3}, [%4];"
                 : "=r"(r0), "=r"(r1), "=r"(r2), "=r"(r3) : "r"(addr));
}
__device__ __forceinline__ void mma16816(float* c, const unsigned* a, unsigned b0, unsigned b1) {
    asm volatile(
        "mma.sync.aligned.m16n8k16.row.col.f32.f16.f16.f32 "
        "{%0,%1,%2,%3}, {%4,%5,%6,%7}, {%8,%9}, {%0,%1,%2,%3};"
        : "+f"(c[0]), "+f"(c[1]), "+f"(c[2]), "+f"(c[3])
        : "r"(a[0]), "r"(a[1]), "r"(a[2]), "r"(a[3]), "r"(b0), "r"(b1));
}

// ---------------- kernels ----------------
// L1: zero degree counters + build W mma-fragment table
__global__ void k_init(const float* __restrict__ W) {
    int i = blockIdx.x * blockDim.x + threadIdx.x;
    if (i < NN) g_cnt[i] = 0;
    int j = i - NN;
    if (j >= 0 && j < NWF) {
        int lane = j & 31, ntg = (j >> 5) & 15, ks = j >> 9;
        int n  = ntg * 8 + (lane >> 2);
        int tq = lane & 3;
        int k0 = ks * 16 + tq * 2;
        __half2 b0 = __floats2half2_rn(W[k0 * FF + n],       W[(k0 + 1) * FF + n]);
        __half2 b1 = __floats2half2_rn(W[(k0 + 8) * FF + n], W[(k0 + 9) * FF + n]);
        uint2 o;
        o.x = *(const unsigned*)&b0;
        o.y = *(const unsigned*)&b1;
        g_Wf[j] = o;
    }
}

// L2: single-pass padded-CSR scatter (atomics, latency-bound) overlapped with
//     meff = sigmoid gating (DRAM-bound). Train-row fixup happens in L3.
__global__ void k_scatter_meff(const int* __restrict__ erow, const int* __restrict__ ecol,
                               const float* __restrict__ aval,
                               const float* __restrict__ x, const float* __restrict__ M) {
    int gi = blockIdx.x * blockDim.x + threadIdx.x;
    if (gi < SCAT_T) {
        int2   r = ((const int2*)erow)[gi];
        int2   c = ((const int2*)ecol)[gi];
        float2 w = ((const float2*)aval)[gi];
        int p0 = atomicAdd(&g_cnt[r.x], 1);
        if (p0 < MAXDEG) g_cv[r.x * MAXDEG + p0] = make_int2(c.x, __float_as_int(w.x));
        int p1 = atomicAdd(&g_cnt[r.y], 1);
        if (p1 < MAXDEG) g_cv[r.y * MAXDEG + p1] = make_int2(c.y, __float_as_int(w.y));
        return;
    }
    int i = gi - SCAT_T;
    if (i >= MEFF_T) return;
    float4 m  = ((const float4*)M)[i];
    float4 xv = ((const float4*)x)[i];
    float4 me, mx;
    me.x = sigmoid_fast(m.x); me.y = sigmoid_fast(m.y);
    me.z = sigmoid_fast(m.z); me.w = sigmoid_fast(m.w);
    mx.x = me.x * xv.x; mx.y = me.y * xv.y;
    mx.z = me.z * xv.z; mx.w = me.w * xv.w;
    H2x4 p;
    p.me01 = __floats2half2_rn(me.x, me.y);
    p.me23 = __floats2half2_rn(me.z, me.w);
    p.mx01 = __floats2half2_rn(mx.x, mx.y);
    p.mx23 = __floats2half2_rn(mx.z, mx.w);
    g_P[i] = p;
}

// L3: overwrite train rows with (Me=1, Mx=x). Duplicate ids write identical data.
__global__ void k_fix(const int* __restrict__ tid, const float* __restrict__ x) {
    int i = blockIdx.x * blockDim.x + threadIdx.x;
    if (i >= NT * 32) return;
    int node = tid[i >> 5];
    int lane = i & 31;
    float4 xv = *(const float4*)&x[node * FF + lane * 4];
    H2x4 p;
    p.me01 = __floats2half2_rn(1.f, 1.f);
    p.me23 = __floats2half2_rn(1.f, 1.f);
    p.mx01 = __floats2half2_rn(xv.x, xv.y);
    p.mx23 = __floats2half2_rn(xv.z, xv.w);
    g_P[node * 32 + lane] = p;
}

// L4: warp-per-row gather-reduce on packed fp16; writes Hn as fp16
__global__ void k_gather() {
    int gt   = blockIdx.x * blockDim.x + threadIdx.x;
    int row  = gt >> 5;
    int lane = gt & 31;
    if (row >= NN) return;
    int deg = g_cnt[row];
    if (deg > MAXDEG) deg = MAXDEG;
    int s = row * MAXDEG, e = s + deg;
    float4 d = make_float4(0.f, 0.f, 0.f, 0.f);
    float4 h = make_float4(0.f, 0.f, 0.f, 0.f);
    int j = s;
    for (; j + 3 < e; j += 4) {
        int2 cv0 = __ldg(&g_cv[j]);
        int2 cv1 = __ldg(&g_cv[j + 1]);
        int2 cv2 = __ldg(&g_cv[j + 2]);
        int2 cv3 = __ldg(&g_cv[j + 3]);
        H2x4 p0 = g_P[cv0.x * 32 + lane];
        H2x4 p1 = g_P[cv1.x * 32 + lane];
        H2x4 p2 = g_P[cv2.x * 32 + lane];
        H2x4 p3 = g_P[cv3.x * 32 + lane];
        float w0 = __int_as_float(cv0.y), w1 = __int_as_float(cv1.y);
        float w2 = __int_as_float(cv2.y), w3 = __int_as_float(cv3.y);
        float2 a, b;
        a = __half22float2(p0.me01); b = __half22float2(p0.me23);
        d.x += a.x; d.y += a.y; d.z += b.x; d.w += b.y;
        a = __half22float2(p0.mx01); b = __half22float2(p0.mx23);
        h.x += w0 * a.x; h.y += w0 * a.y; h.z += w0 * b.x; h.w += w0 * b.y;
        a = __half22float2(p1.me01); b = __half22float2(p1.me23);
        d.x += a.x; d.y += a.y; d.z += b.x; d.w += b.y;
        a = __half22float2(p1.mx01); b = __half22float2(p1.mx23);
        h.x += w1 * a.x; h.y += w1 * a.y; h.z += w1 * b.x; h.w += w1 * b.y;
        a = __half22float2(p2.me01); b = __half22float2(p2.me23);
        d.x += a.x; d.y += a.y; d.z += b.x; d.w += b.y;
        a = __half22float2(p2.mx01); b = __half22float2(p2.mx23);
        h.x += w2 * a.x; h.y += w2 * a.y; h.z += w2 * b.x; h.w += w2 * b.y;
        a = __half22float2(p3.me01); b = __half22float2(p3.me23);
        d.x += a.x; d.y += a.y; d.z += b.x; d.w += b.y;
        a = __half22float2(p3.mx01); b = __half22float2(p3.mx23);
        h.x += w3 * a.x; h.y += w3 * a.y; h.z += w3 * b.x; h.w += w3 * b.y;
    }
    for (; j < e; ++j) {
        int2 cv = __ldg(&g_cv[j]);
        H2x4 p = g_P[cv.x * 32 + lane];
        float w = __int_as_float(cv.y);
        float2 a, b;
        a = __half22float2(p.me01); b = __half22float2(p.me23);
        d.x += a.x; d.y += a.y; d.z += b.x; d.w += b.y;
        a = __half22float2(p.mx01); b = __half22float2(p.mx23);
        h.x += w * a.x; h.y += w * a.y; h.z += w * b.x; h.w += w * b.y;
    }
    float4 o;
    o.x = (d.x != 0.f) ? h.x * __fdividef(1.f, d.x) : 0.f;
    o.y = (d.y != 0.f) ? h.y * __fdividef(1.f, d.y) : 0.f;
    o.z = (d.z != 0.f) ? h.z * __fdividef(1.f, d.z) : 0.f;
    o.w = (d.w != 0.f) ? h.w * __fdividef(1.f, d.w) : 0.f;
    __half2 h01 = __floats2half2_rn(o.x, o.y);
    __half2 h23 = __floats2half2_rn(o.z, o.w);
    uint2 ph;
    ph.x = *(const unsigned*)&h01;
    ph.y = *(const unsigned*)&h23;
    *(uint2*)&g_Hh[row * FF + lane * 4] = ph;
}

// L5: out = elu(Hh @ W) via mma.sync m16n8k16 fp16->fp32.
// 256 thr / 8 warps; tile 64 rows x 128 cols; warp = 16 rows x 64 cols.
__global__ void k_gemm(float* __restrict__ out) {
    __shared__ __half Hs[GROWS * HS_STRIDE];
    int r0 = blockIdx.x * GROWS;
    int t  = threadIdx.x;

    for (int i = t; i < GROWS * 16; i += 256) {
        int row = i >> 4, c8 = (i & 15) * 8;
        uint4 v = (r0 + row < NN) ? *(const uint4*)&g_Hh[(r0 + row) * FF + c8]
                                  : make_uint4(0u, 0u, 0u, 0u);
        *(uint4*)&Hs[row * HS_STRIDE + c8] = v;
    }
    __syncthreads();

    int wid = t >> 5, lane = t & 31;
    int wm = wid >> 1, wn = wid & 1;

    unsigned a[8][4];
    int sub = lane >> 3, rr = lane & 7;
    int arow = wm * 16 + rr + (sub & 1) * 8;
    int acol = (sub >> 1) * 8;
    #pragma unroll
    for (int ks = 0; ks < 8; ks++) {
        unsigned addr = (unsigned)__cvta_generic_to_shared(&Hs[arow * HS_STRIDE + ks * 16 + acol]);
        ldm_x4(a[ks][0], a[ks][1], a[ks][2], a[ks][3], addr);
    }

    float acc[8][4] = {};
    #pragma unroll
    for (int ks = 0; ks < 8; ks++) {
        #pragma unroll
        for (int nt = 0; nt < 8; nt++) {
            uint2 b = __ldg(&g_Wf[(ks * 16 + wn * 8 + nt) * 32 + lane]);
            mma16816(acc[nt], a[ks], b.x, b.y);
        }
    }

    int g = lane >> 2, tq = lane & 3;
    int row0 = r0 + wm * 16 + g;
    int row1 = row0 + 8;
    #pragma unroll
    for (int nt = 0; nt < 8; nt++) {
        int col = wn * 64 + nt * 8 + 2 * tq;
        if (row0 < NN) {
            float2 v;
            v.x = elu1(acc[nt][0]);
            v.y = elu1(acc[nt][1]);
            *(float2*)&out[row0 * FF + col] = v;
        }
        if (row1 < NN) {
            float2 v;
            v.x = elu1(acc[nt][2]);
            v.y = elu1(acc[nt][3]);
            *(float2*)&out[row1 * FF + col] = v;
        }
    }
}

// ---------------- launch ----------------
extern "C" void kernel_launch(void* const* d_in, const int* in_sizes, int n_in,
                              void* d_out, int out_size) {
    const float* x    = (const float*)d_in[0];
    const int*   erow = (const int*)  d_in[1];
    const int*   ecol = (const int*)  d_in[2];
    const float* aval = (const float*)d_in[3];
    const int*   tid  = (const int*)  d_in[4];
    const float* M    = (const float*)d_in[5];
    const float* W    = (const float*)d_in[6];
    float*       out  = (float*)d_out;

    k_init        <<<(NN + NWF + 255) / 256, 256>>>(W);
    k_scatter_meff<<<(SCAT_T + MEFF_T + 255) / 256, 256>>>(erow, ecol, aval, x, M);
    k_fix         <<<(NT * 32 + 255) / 256, 256>>>(tid, x);
    k_gather      <<<(NN * 32 + 255) / 256, 256>>>();
    k_gemm        <<<(NN + GROWS - 1) / GROWS, 256>>>(out);
}

// round 10
// speedup vs baseline: 1.9330x; 1.0817x over previous
#include <cuda_runtime.h>
#include <cuda_fp16.h>
#include <math.h>

#define NN 50000
#define FF 128
#define NE 800000
#define NT 5000
#define NWF 4096               // 8 ksteps * 16 ntiles * 32 lanes
#define SCAT_T (NE / 2)        // 400000 scatter threads (2 edges each)
#define MEFF_T (NN * 32)       // 1600000 meff quad threads
#define MAXDEG 128             // padded CSR row capacity (P(overflow) ~ 1e-68)
#define GROWS 64               // rows per fused block
#define HS_STRIDE 136          // padded fp16 row stride in smem

// ---------------- static device scratch (no allocations allowed) ----------------
struct __align__(16) H2x4 { __half2 me01, me23, mx01, mx23; };
static __device__ H2x4  g_P[NN * 32];          // packed (Me, Mx) fp16, 25.6 MB
static __device__ uint2 g_Wf[NWF];             // W fp16 in mma B-fragment layout, 32 KB
static __device__ int   g_cnt[NN];             // degree counter / CSR fill cursor
static __device__ int2  g_cv[NN * MAXDEG];     // padded CSR (col, val-bits), 51.2 MB

// ---------------- helpers ----------------
__device__ __forceinline__ float sigmoid_fast(float z) {
    return 1.0f / (1.0f + __expf(-z));
}
__device__ __forceinline__ float elu1(float v) {
    return v > 0.0f ? v : expm1f(v);
}
__device__ __forceinline__ void ldm_x4(unsigned& r0, unsigned& r1, unsigned& r2, unsigned& r3,
                                       unsigned addr) {
    asm volatile("ldmatrix.sync.aligned.m8n8.x4.shared.b16 {%0,%1,%2,%3}, [%4];"
                 : "=r"(r0), "=r"(r1), "=r"(r2), "=r"(r3) : "r"(addr));
}
__device__ __forceinline__ void mma16816(float* c, const unsigned* a, unsigned b0, unsigned b1) {
    asm volatile(
        "mma.sync.aligned.m16n8k16.row.col.f32.f16.f16.f32 "
        "{%0,%1,%2,%3}, {%4,%5,%6,%7}, {%8,%9}, {%0,%1,%2,%3};"
        : "+f"(c[0]), "+f"(c[1]), "+f"(c[2]), "+f"(c[3])
        : "r"(a[0]), "r"(a[1]), "r"(a[2]), "r"(a[3]), "r"(b0), "r"(b1));
}
// accumulate one edge: d += Me[col], h += w * Mx[col]
__device__ __forceinline__ void acc_edge(int col, float w, int lane, float4& d, float4& h) {
    H2x4 p = g_P[col * 32 + lane];
    float2 a, b;
    a = __half22float2(p.me01); b = __half22float2(p.me23);
    d.x += a.x; d.y += a.y; d.z += b.x; d.w += b.y;
    a = __half22float2(p.mx01); b = __half22float2(p.mx23);
    h.x += w * a.x; h.y += w * a.y; h.z += w * b.x; h.w += w * b.y;
}

// ---------------- kernels ----------------
// L1: zero degree counters + build W mma-fragment table
__global__ void k_init(const float* __restrict__ W) {
    int i = blockIdx.x * blockDim.x + threadIdx.x;
    if (i < NN) g_cnt[i] = 0;
    int j = i - NN;
    if (j >= 0 && j < NWF) {
        int lane = j & 31, ntg = (j >> 5) & 15, ks = j >> 9;
        int n  = ntg * 8 + (lane >> 2);
        int tq = lane & 3;
        int k0 = ks * 16 + tq * 2;
        __half2 b0 = __floats2half2_rn(W[k0 * FF + n],       W[(k0 + 1) * FF + n]);
        __half2 b1 = __floats2half2_rn(W[(k0 + 8) * FF + n], W[(k0 + 9) * FF + n]);
        uint2 o;
        o.x = *(const unsigned*)&b0;
        o.y = *(const unsigned*)&b1;
        g_Wf[j] = o;
    }
}

// L2: single-pass padded-CSR scatter (atomics) overlapped with meff gating (DRAM-bound)
__global__ void k_scatter_meff(const int* __restrict__ erow, const int* __restrict__ ecol,
                               const float* __restrict__ aval,
                               const float* __restrict__ x, const float* __restrict__ M) {
    int gi = blockIdx.x * blockDim.x + threadIdx.x;
    if (gi < SCAT_T) {
        int2   r = ((const int2*)erow)[gi];
        int2   c = ((const int2*)ecol)[gi];
        float2 w = ((const float2*)aval)[gi];
        int p0 = atomicAdd(&g_cnt[r.x], 1);
        if (p0 < MAXDEG) g_cv[r.x * MAXDEG + p0] = make_int2(c.x, __float_as_int(w.x));
        int p1 = atomicAdd(&g_cnt[r.y], 1);
        if (p1 < MAXDEG) g_cv[r.y * MAXDEG + p1] = make_int2(c.y, __float_as_int(w.y));
        return;
    }
    int i = gi - SCAT_T;
    if (i >= MEFF_T) return;
    float4 m  = ((const float4*)M)[i];
    float4 xv = ((const float4*)x)[i];
    float4 me, mx;
    me.x = sigmoid_fast(m.x); me.y = sigmoid_fast(m.y);
    me.z = sigmoid_fast(m.z); me.w = sigmoid_fast(m.w);
    mx.x = me.x * xv.x; mx.y = me.y * xv.y;
    mx.z = me.z * xv.z; mx.w = me.w * xv.w;
    H2x4 p;
    p.me01 = __floats2half2_rn(me.x, me.y);
    p.me23 = __floats2half2_rn(me.z, me.w);
    p.mx01 = __floats2half2_rn(mx.x, mx.y);
    p.mx23 = __floats2half2_rn(mx.z, mx.w);
    g_P[i] = p;
}

// L3: overwrite train rows with (Me=1, Mx=x). Duplicate ids write identical data.
__global__ void k_fix(const int* __restrict__ tid, const float* __restrict__ x) {
    int i = blockIdx.x * blockDim.x + threadIdx.x;
    if (i >= NT * 32) return;
    int node = tid[i >> 5];
    int lane = i & 31;
    float4 xv = *(const float4*)&x[node * FF + lane * 4];
    H2x4 p;
    p.me01 = __floats2half2_rn(1.f, 1.f);
    p.me23 = __floats2half2_rn(1.f, 1.f);
    p.mx01 = __floats2half2_rn(xv.x, xv.y);
    p.mx23 = __floats2half2_rn(xv.z, xv.w);
    g_P[node * 32 + lane] = p;
}

// L4 (fused): gather 64 rows into smem, then out = elu(Hs @ W) via mma.sync.
// 256 thr / 8 warps. Gather: warp w owns rows [r0+8w, r0+8w+8). GEMM: warp = 16r x 64c.
__global__ void __launch_bounds__(256, 4) k_gg(float* __restrict__ out) {
    __shared__ __half Hs[GROWS * HS_STRIDE];
    int r0 = blockIdx.x * GROWS;
    int t  = threadIdx.x;
    int wid = t >> 5, lane = t & 31;

    // ---- phase 1: gather-reduce 8 rows per warp ----
    for (int rr = 0; rr < 8; rr++) {
        int lr  = wid * 8 + rr;
        int row = r0 + lr;
        __half* hdst = &Hs[lr * HS_STRIDE + lane * 4];
        if (row >= NN) {
            *(uint2*)hdst = make_uint2(0u, 0u);
            continue;
        }
        int deg = g_cnt[row];
        if (deg > MAXDEG) deg = MAXDEG;
        const int4* cp = (const int4*)&g_cv[row * MAXDEG];   // 2 edges per int4
        float4 d = make_float4(0.f, 0.f, 0.f, 0.f);
        float4 h = make_float4(0.f, 0.f, 0.f, 0.f);
        int npair = deg >> 1;
        int j = 0;
        for (; j + 1 < npair; j += 2) {       // 4 edges
            int4 q0 = __ldg(&cp[j]);
            int4 q1 = __ldg(&cp[j + 1]);
            acc_edge(q0.x, __int_as_float(q0.y), lane, d, h);
            acc_edge(q0.z, __int_as_float(q0.w), lane, d, h);
            acc_edge(q1.x, __int_as_float(q1.y), lane, d, h);
            acc_edge(q1.z, __int_as_float(q1.w), lane, d, h);
        }
        if (j < npair) {                      // 2 edges
            int4 q = __ldg(&cp[j]);
            acc_edge(q.x, __int_as_float(q.y), lane, d, h);
            acc_edge(q.z, __int_as_float(q.w), lane, d, h);
        }
        if (deg & 1) {                        // last edge
            int2 cv = __ldg(&g_cv[row * MAXDEG + deg - 1]);
            acc_edge(cv.x, __int_as_float(cv.y), lane, d, h);
        }
        float4 o;
        o.x = (d.x != 0.f) ? h.x * __fdividef(1.f, d.x) : 0.f;
        o.y = (d.y != 0.f) ? h.y * __fdividef(1.f, d.y) : 0.f;
        o.z = (d.z != 0.f) ? h.z * __fdividef(1.f, d.z) : 0.f;
        o.w = (d.w != 0.f) ? h.w * __fdividef(1.f, d.w) : 0.f;
        __half2 h01 = __floats2half2_rn(o.x, o.y);
        __half2 h23 = __floats2half2_rn(o.z, o.w);
        uint2 ph;
        ph.x = *(const unsigned*)&h01;
        ph.y = *(const unsigned*)&h23;
        *(uint2*)hdst = ph;
    }
    __syncthreads();

    // ---- phase 2: mma GEMM on the smem tile ----
    int wm = wid >> 1, wn = wid & 1;
    int sub = lane >> 3, rr8 = lane & 7;
    int arow = wm * 16 + rr8 + (sub & 1) * 8;
    int acol = (sub >> 1) * 8;

    float acc[8][4] = {};
    #pragma unroll
    for (int ks = 0; ks < 8; ks++) {
        unsigned a[4];
        unsigned addr = (unsigned)__cvta_generic_to_shared(&Hs[arow * HS_STRIDE + ks * 16 + acol]);
        ldm_x4(a[0], a[1], a[2], a[3], addr);
        #pragma unroll
        for (int nt = 0; nt < 8; nt++) {
            uint2 b = __ldg(&g_Wf[(ks * 16 + wn * 8 + nt) * 32 + lane]);
            mma16816(acc[nt], a, b.x, b.y);
        }
    }

    int g = lane >> 2, tq = lane & 3;
    int row0 = r0 + wm * 16 + g;
    int row1 = row0 + 8;
    #pragma unroll
    for (int nt = 0; nt < 8; nt++) {
        int col = wn * 64 + nt * 8 + 2 * tq;
        if (row0 < NN) {
            float2 v;
            v.x = elu1(acc[nt][0]);
            v.y = elu1(acc[nt][1]);
            *(float2*)&out[row0 * FF + col] = v;
        }
        if (row1 < NN) {
            float2 v;
            v.x = elu1(acc[nt][2]);
            v.y = elu1(acc[nt][3]);
            *(float2*)&out[row1 * FF + col] = v;
        }
    }
}

// ---------------- launch ----------------
extern "C" void kernel_launch(void* const* d_in, const int* in_sizes, int n_in,
                              void* d_out, int out_size) {
    const float* x    = (const float*)d_in[0];
    const int*   erow = (const int*)  d_in[1];
    const int*   ecol = (const int*)  d_in[2];
    const float* aval = (const float*)d_in[3];
    const int*   tid  = (const int*)  d_in[4];
    const float* M    = (const float*)d_in[5];
    const float* W    = (const float*)d_in[6];
    float*       out  = (float*)d_out;

    k_init        <<<(NN + NWF + 255) / 256, 256>>>(W);
    k_scatter_meff<<<(SCAT_T + MEFF_T + 255) / 256, 256>>>(erow, ecol, aval, x, M);
    k_fix         <<<(NT * 32 + 255) / 256, 256>>>(tid, x);
    k_gg          <<<(NN + GROWS - 1) / GROWS, 256>>>(out);
}